// round 1
// baseline (speedup 1.0000x reference)
#include <cuda_runtime.h>
#include <cstdint>
#include <cstddef>

#define BM 128
#define BN 64
#define BK 32
#define PAD 4
#define ASTRIDE (BK + PAD)   // 36 floats: row starts 144B apart (16B aligned), conflict-free frag loads
#define KDIM 512
#define NRE 257
#define NTOT 514
#define THREADS 256
#define SMEM_FLOATS (2 * BM * ASTRIDE + 2 * BN * ASTRIDE)
#define SMEM_BYTES (SMEM_FLOATS * 4)

__device__ __forceinline__ uint32_t f2tf32(float f) {
    uint32_t r;
    asm volatile("cvt.rna.tf32.f32 %0, %1;\n" : "=r"(r) : "f"(f));
    return r;
}

__device__ __forceinline__ void mma_tf32(float& c0, float& c1, float& c2, float& c3,
                                         uint32_t a0, uint32_t a1, uint32_t a2, uint32_t a3,
                                         uint32_t b0, uint32_t b1) {
    asm volatile(
        "mma.sync.aligned.m16n8k8.row.col.f32.tf32.tf32.f32 "
        "{%0,%1,%2,%3}, {%4,%5,%6,%7}, {%8,%9}, {%0,%1,%2,%3};\n"
        : "+f"(c0), "+f"(c1), "+f"(c2), "+f"(c3)
        : "r"(a0), "r"(a1), "r"(a2), "r"(a3), "r"(b0), "r"(b1));
}

__device__ __forceinline__ void cp_async16(float* dst_smem, const float* src) {
    uint32_t dst = (uint32_t)__cvta_generic_to_shared(dst_smem);
    asm volatile("cp.async.cg.shared.global [%0], [%1], 16;\n" :: "r"(dst), "l"(src));
}

__device__ __forceinline__ void cp_async16_zfill(float* dst_smem, const float* src, int nbytes) {
    uint32_t dst = (uint32_t)__cvta_generic_to_shared(dst_smem);
    asm volatile("cp.async.cg.shared.global [%0], [%1], 16, %2;\n" :: "r"(dst), "l"(src), "r"(nbytes));
}

__device__ __forceinline__ void load_tile_A(const float* __restrict__ X, float* As,
                                            int m0, int k0, int tid) {
#pragma unroll
    for (int i = 0; i < 4; i++) {
        int idx = tid + i * THREADS;          // 0..1023
        int row = idx >> 3;                   // 0..127
        int ch  = idx & 7;                    // 0..7 (16B chunks)
        const float* src = X + (size_t)(m0 + row) * KDIM + k0 + ch * 4;
        cp_async16(As + row * ASTRIDE + ch * 4, src);
    }
}

__device__ __forceinline__ void load_tile_B(const float* __restrict__ MR, const float* __restrict__ MI,
                                            float* Bs, int n0, int k0, int tid) {
#pragma unroll
    for (int i = 0; i < 2; i++) {
        int idx = tid + i * THREADS;          // 0..511
        int row = idx >> 3;                   // 0..63
        int ch  = idx & 7;
        int ng = n0 + row;
        const float* src;
        int nb = 16;
        if (ng < NRE) {
            src = MR + (size_t)ng * KDIM + k0 + ch * 4;
        } else if (ng < NTOT) {
            src = MI + (size_t)(ng - NRE) * KDIM + k0 + ch * 4;
        } else {
            src = MR;   // valid address, zero-filled
            nb = 0;
        }
        cp_async16_zfill(Bs + row * ASTRIDE + ch * 4, src, nb);
    }
}

__device__ __forceinline__ void compute_tile(const float* As, const float* Bs,
                                             int wm, int wn, int lane,
                                             float acc[2][4][4]) {
    const int g = lane >> 2;   // group id 0..7
    const int t = lane & 3;    // thread-in-group 0..3
#pragma unroll
    for (int ks = 0; ks < 4; ks++) {
        const int k = ks * 8;
        uint32_t a[2][4];
        uint32_t b[4][2];
#pragma unroll
        for (int mi = 0; mi < 2; mi++) {
            const float* base = As + (wm * 32 + mi * 16 + g) * ASTRIDE + k + t;
            a[mi][0] = f2tf32(base[0]);
            a[mi][1] = f2tf32(base[8 * ASTRIDE]);
            a[mi][2] = f2tf32(base[4]);
            a[mi][3] = f2tf32(base[8 * ASTRIDE + 4]);
        }
#pragma unroll
        for (int ni = 0; ni < 4; ni++) {
            const float* base = Bs + (wn * 32 + ni * 8 + g) * ASTRIDE + k + t;
            b[ni][0] = f2tf32(base[0]);
            b[ni][1] = f2tf32(base[4]);
        }
#pragma unroll
        for (int mi = 0; mi < 2; mi++)
#pragma unroll
            for (int ni = 0; ni < 4; ni++)
                mma_tf32(acc[mi][ni][0], acc[mi][ni][1], acc[mi][ni][2], acc[mi][ni][3],
                         a[mi][0], a[mi][1], a[mi][2], a[mi][3],
                         b[ni][0], b[ni][1]);
    }
}

__device__ __forceinline__ void store_c(float* __restrict__ re, float* __restrict__ im,
                                        int r, int c, float v) {
    if (c < NRE) {
        re[(size_t)r * NRE + c] = v;
    } else if (c < NTOT) {
        im[(size_t)r * NRE + (c - NRE)] = v;
    }
}

__global__ void __launch_bounds__(THREADS)
rfft_gemm_kernel(const float* __restrict__ X, const float* __restrict__ MR,
                 const float* __restrict__ MI, float* __restrict__ OUT, int M) {
    const int bn = blockIdx.x;
    const int bm = blockIdx.y;
    const int m0 = bm * BM;
    const int n0 = bn * BN;
    const int tid = threadIdx.x;
    const int lane = tid & 31;
    const int w = tid >> 5;
    const int wm = w & 3;     // 4 warps in M
    const int wn = w >> 2;    // 2 warps in N

    extern __shared__ float smem[];
    float* As[2] = { smem, smem + BM * ASTRIDE };
    float* Bs[2] = { smem + 2 * BM * ASTRIDE, smem + 2 * BM * ASTRIDE + BN * ASTRIDE };

    float acc[2][4][4];
#pragma unroll
    for (int mi = 0; mi < 2; mi++)
#pragma unroll
        for (int ni = 0; ni < 4; ni++)
#pragma unroll
            for (int j = 0; j < 4; j++)
                acc[mi][ni][j] = 0.0f;

    load_tile_A(X, As[0], m0, 0, tid);
    load_tile_B(MR, MI, Bs[0], n0, 0, tid);
    asm volatile("cp.async.commit_group;\n" ::: "memory");

    const int KT = KDIM / BK;   // 16
#pragma unroll 1
    for (int kt = 0; kt < KT; kt++) {
        if (kt + 1 < KT) {
            load_tile_A(X, As[(kt + 1) & 1], m0, (kt + 1) * BK, tid);
            load_tile_B(MR, MI, Bs[(kt + 1) & 1], n0, (kt + 1) * BK, tid);
            asm volatile("cp.async.commit_group;\n" ::: "memory");
            asm volatile("cp.async.wait_group 1;\n" ::: "memory");
        } else {
            asm volatile("cp.async.wait_group 0;\n" ::: "memory");
        }
        __syncthreads();
        compute_tile(As[kt & 1], Bs[kt & 1], wm, wn, lane, acc);
        __syncthreads();
    }

    // Epilogue: scatter accumulators to re / im halves of OUT.
    float* re = OUT;
    float* im = OUT + (size_t)M * NRE;
    const int g = lane >> 2;
    const int t = lane & 3;
#pragma unroll
    for (int mi = 0; mi < 2; mi++) {
#pragma unroll
        for (int ni = 0; ni < 4; ni++) {
            int r0 = m0 + wm * 32 + mi * 16 + g;
            int cb = n0 + wn * 32 + ni * 8 + 2 * t;
            store_c(re, im, r0,     cb,     acc[mi][ni][0]);
            store_c(re, im, r0,     cb + 1, acc[mi][ni][1]);
            store_c(re, im, r0 + 8, cb,     acc[mi][ni][2]);
            store_c(re, im, r0 + 8, cb + 1, acc[mi][ni][3]);
        }
    }
}

extern "C" void kernel_launch(void* const* d_in, const int* in_sizes, int n_in,
                              void* d_out, int out_size) {
    const float* X  = (const float*)d_in[0];
    const float* MR = (const float*)d_in[1];
    const float* MI = (const float*)d_in[2];
    float* OUT = (float*)d_out;
    const int M = in_sizes[0] / KDIM;   // 128000

    cudaFuncSetAttribute(rfft_gemm_kernel, cudaFuncAttributeMaxDynamicSharedMemorySize, SMEM_BYTES);

    dim3 grid((NTOT + BN - 1) / BN, M / BM);   // (9, 1000)
    rfft_gemm_kernel<<<grid, THREADS, SMEM_BYTES>>>(X, MR, MI, OUT, M);
}